// round 7
// baseline (speedup 1.0000x reference)
#include <cuda_runtime.h>
#include <stdint.h>

// FP32 bit-pulse -> FP8 E4M3 bit-pulse converter.
// Input:  N*32 floats, exactly 0.0/1.0, per value [S, E7..E0, M22..M0] (MSB first)
// Output: N*8  floats, per value [S, E3..E0, M2..M0]
//
// Round-7: decoupled streaming. cp.async.bulk (UBLKCP) double-buffers 16 KB
// input chunks into smem behind mbarriers — the bulk engine owns the DRAM read
// stream, so consumer scheduling can no longer throttle memory demand. Consumer
// warps run the ballot reconstruction against smem (LDS lat 29, conflict-free:
// lanes read 32 consecutive floats) and write contiguous float4 streaming
// stores directly to GMEM.

#define WARPS_PER_BLOCK 4
#define THREADS (WARPS_PER_BLOCK * 32)
#define CHUNK_VALS   128                       // values per stage (4 warps * 32)
#define CHUNK_FLOATS (CHUNK_VALS * 32)         // 4096 floats = 16 KB
#define CHUNK_BYTES  (CHUNK_FLOATS * 4)
#define STAGES 2

__device__ __forceinline__ uint32_t smem_u32(const void* p) {
    uint32_t a;
    asm("{ .reg .u64 t; cvta.to.shared.u64 t, %1; cvt.u32.u64 %0, t; }"
        : "=r"(a) : "l"(p));
    return a;
}

__global__ void __launch_bounds__(THREADS)
fp32_to_fp8_pulse_kernel(const float* __restrict__ in,
                         float* __restrict__ out,
                         int nchunks)
{
    __shared__ __align__(16) float    buf[STAGES][CHUNK_FLOATS];   // 32 KB
    __shared__ __align__(8)  uint64_t mbar[STAGES];

    const int tid  = threadIdx.x;
    const int lane = tid & 31;
    const int wrp  = tid >> 5;

    if (tid == 0) {
        asm volatile("mbarrier.init.shared.b64 [%0], 1;" :: "r"(smem_u32(&mbar[0])));
        asm volatile("mbarrier.init.shared.b64 [%0], 1;" :: "r"(smem_u32(&mbar[1])));
        asm volatile("fence.proxy.async.shared::cta;" ::: "memory");
    }
    __syncthreads();

    // Chunks for this block: c_k = blockIdx.x + k*gridDim.x, k = 0..K-1.
    const int K = (nchunks - blockIdx.x + gridDim.x - 1) / gridDim.x;
    if (K <= 0) return;   // grid <= nchunks, so never taken; safety only

    auto issue = [&](int k) {
        const int c      = blockIdx.x + k * gridDim.x;
        const int stage  = k & 1;
        const uint32_t mb  = smem_u32(&mbar[stage]);
        const uint32_t dst = smem_u32(&buf[stage][0]);
        const float* src = in + (size_t)c * CHUNK_FLOATS;
        asm volatile("mbarrier.arrive.expect_tx.shared.b64 _, [%0], %1;"
                     :: "r"(mb), "r"((uint32_t)CHUNK_BYTES) : "memory");
        asm volatile("cp.async.bulk.shared::cta.global.mbarrier::complete_tx::bytes "
                     "[%0], [%1], %2, [%3];"
                     :: "r"(dst), "l"(src), "r"((uint32_t)CHUNK_BYTES), "r"(mb)
                     : "memory");
    };

    if (tid == 0) issue(0);

    for (int k = 0; k < K; k++) {
        // Prefetch next chunk into the other buffer (consumed 2 iterations ago,
        // protected by last iteration's __syncthreads).
        if (tid == 0 && k + 1 < K) issue(k + 1);

        // Wait for this stage's data (acquire orders the LDS reads below).
        const int stage = k & 1;
        const uint32_t parity = (k >> 1) & 1;
        const uint32_t mb = smem_u32(&mbar[stage]);
        uint32_t done;
        asm volatile("{ .reg .pred p; "
                     "mbarrier.try_wait.parity.acquire.cta.shared::cta.b64 p, [%1], %2; "
                     "selp.b32 %0, 1, 0, p; }"
                     : "=r"(done) : "r"(mb), "r"(parity) : "memory");
        while (!done) {
            asm volatile("{ .reg .pred p; "
                         "mbarrier.try_wait.parity.acquire.cta.shared::cta.b64 p, [%1], %2, 0x989680; "
                         "selp.b32 %0, 1, 0, p; }"
                         : "=r"(done) : "r"(mb), "r"(parity) : "memory");
        }

        // Consume: warp wrp handles values [wrp*32, wrp*32+32) of this chunk.
        // Lane l reads bit-pulse l of value i (consecutive floats -> conflict-free).
        const float* sf = &buf[stage][wrp * 32 * 32];
        uint32_t word = 0;
#pragma unroll
        for (int i = 0; i < 32; i++) {
            float f = sf[i * 32 + lane];
            uint32_t b = __ballot_sync(0xFFFFFFFFu, f > 0.5f);
            if (lane == i) word = b;
        }
        word = __brev(word);   // standard IEEE fp32 bit pattern

        const uint32_t s    = word >> 31;
        const uint32_t exp  = (word >> 23) & 0xFFu;
        const uint32_t mant = word & 0x7FFFFFu;

        // ---- normal path: fp8_exp = exp - 120, RNE round 23 -> 3 bits ----
        uint32_t kept  = mant >> 20;
        uint32_t R     = (mant >> 19) & 1u;
        uint32_t S     = (mant & 0x7FFFFu) ? 1u : 0u;
        uint32_t L     = kept & 1u;
        uint32_t mr    = kept + (R & (S | L));
        uint32_t carry = mr >> 3;
        uint32_t mant_norm = carry ? 0u : (mr & 7u);
        int exp_norm = (int)exp - 120 + (int)carry;

        // ---- subnormal path (117 <= exp <= 120) ----
        uint32_t full = (1u << 23) | mant;
        int sh = 141 - (int)exp;
        sh = sh < 1 ? 1 : (sh > 24 ? 24 : sh);
        uint32_t kept_s = full >> sh;
        uint32_t Rs = (full >> (sh - 1)) & 1u;
        uint32_t Ss = (full & ((1u << (sh - 1)) - 1u)) ? 1u : 0u;
        uint32_t Ls = kept_s & 1u;
        uint32_t ms = kept_s + (Rs & (Ss | Ls));
        uint32_t sub_exp  = (ms >= 8u) ? 1u : 0u;
        uint32_t sub_mant = (ms >= 8u) ? 0u : ms;

        // ---- select overflow / subnormal / underflow / normal ----
        uint32_t exp8, mant8;
        if (exp > 134u) {
            exp8 = 15u; mant8 = 6u;
        } else if (exp >= 117u) {
            if (exp <= 120u) { exp8 = sub_exp; mant8 = sub_mant; }
            else             { exp8 = (uint32_t)exp_norm; mant8 = mant_norm; }
        } else {
            exp8 = 0u; mant8 = 0u;         // underflow
        }

        float4 o0 = make_float4((float)s,
                                (float)((exp8 >> 3) & 1u),
                                (float)((exp8 >> 2) & 1u),
                                (float)((exp8 >> 1) & 1u));
        float4 o1 = make_float4((float)(exp8 & 1u),
                                (float)((mant8 >> 2) & 1u),
                                (float)((mant8 >> 1) & 1u),
                                (float)(mant8 & 1u));

        const int c = blockIdx.x + k * gridDim.x;
        float4* op = reinterpret_cast<float4*>(
            out + ((size_t)c * CHUNK_VALS + wrp * 32 + lane) * 8);
        __stcs(&op[0], o0);
        __stcs(&op[1], o1);

        // All warps done with buf[stage] before it is refilled at k+2.
        __syncthreads();
    }
}

extern "C" void kernel_launch(void* const* d_in, const int* in_sizes, int n_in,
                              void* d_out, int out_size)
{
    const float* in  = (const float*)d_in[0];
    float*       out = (float*)d_out;
    const int nvals   = in_sizes[0] / 32;              // 2,097,152
    const int nchunks = nvals / CHUNK_VALS;            // 16,384 (exact)

    int grid = 1024;                                   // 16 chunks per block
    if (grid > nchunks) grid = nchunks;

    fp32_to_fp8_pulse_kernel<<<grid, THREADS>>>(in, out, nchunks);
}

// round 8
// speedup vs baseline: 1.2877x; 1.2877x over previous
#include <cuda_runtime.h>
#include <stdint.h>

// FP32 bit-pulse -> FP8 E4M3 bit-pulse converter.
// Input:  N*32 floats, each 0.0/1.0, per value [S, E7..E0, M22..M0] (MSB first)
// Output: N*8  floats, per value [S, E3..E0, M2..M0]
//
// Final structure (round-4 winner): lane l loads float (v*32 + l);
// __brev(__ballot(f > 0.5)) IS the IEEE-754 fp32 bit pattern of value v.
// Streaming cache hints (__ldcs/__stcs) keep the zero-reuse read and write
// streams from thrashing L2. Round-8: 512-thread blocks (16 warps) for a
// deeper per-SMSP warp pool; per-warp code identical.
//
// Profiling across 7 rounds shows this shape runs at ~80% of HBM spec with no
// other pipe above 50% and latency fully covered — i.e. at the practical
// mixed read/write HBM wall for this part.

__global__ void __launch_bounds__(512)
fp32_to_fp8_pulse_kernel(const float* __restrict__ in,
                         float* __restrict__ out,
                         int nvals)
{
    const int lane    = threadIdx.x & 31;
    const int warp_id = (blockIdx.x * blockDim.x + threadIdx.x) >> 5;
    const int base    = warp_id * 32;           // 32 values per warp
    if (base >= nvals) return;

    const float* p = in + (size_t)base * 32;

    // Gather + ballot: iteration i reconstructs value (base + i); lane i keeps it.
    uint32_t word = 0;
#pragma unroll
    for (int i = 0; i < 32; i++) {
        float f = __ldcs(&p[i * 32 + lane]);    // streaming load, evict-first
        uint32_t b = __ballot_sync(0xFFFFFFFFu, f > 0.5f);
        if (lane == i) word = b;
    }
    word = __brev(word);   // standard IEEE fp32 bit pattern

    const uint32_t s    = word >> 31;
    const uint32_t exp  = (word >> 23) & 0xFFu;
    const uint32_t mant = word & 0x7FFFFFu;

    // ---- normal path: fp8_exp = exp - 120, RNE round 23 -> 3 mantissa bits ----
    uint32_t kept  = mant >> 20;
    uint32_t R     = (mant >> 19) & 1u;
    uint32_t S     = (mant & 0x7FFFFu) ? 1u : 0u;
    uint32_t L     = kept & 1u;
    uint32_t mr    = kept + (R & (S | L));
    uint32_t carry = mr >> 3;
    uint32_t mant_norm = carry ? 0u : (mr & 7u);
    int exp_norm = (int)exp - 120 + (int)carry;

    // ---- subnormal path (117 <= exp <= 120): shift 1.mant right, RNE ----
    uint32_t full = (1u << 23) | mant;
    int sh = 141 - (int)exp;
    sh = sh < 1 ? 1 : (sh > 24 ? 24 : sh);
    uint32_t kept_s = full >> sh;
    uint32_t Rs = (full >> (sh - 1)) & 1u;
    uint32_t Ss = (full & ((1u << (sh - 1)) - 1u)) ? 1u : 0u;
    uint32_t Ls = kept_s & 1u;
    uint32_t ms = kept_s + (Rs & (Ss | Ls));
    uint32_t sub_exp  = (ms >= 8u) ? 1u : 0u;
    uint32_t sub_mant = (ms >= 8u) ? 0u : ms;

    // ---- select overflow / subnormal / underflow / normal ----
    uint32_t exp8, mant8;
    if (exp > 134u) {
        exp8 = 15u; mant8 = 6u;
    } else if (exp >= 117u) {
        if (exp <= 120u) { exp8 = sub_exp; mant8 = sub_mant; }
        else             { exp8 = (uint32_t)exp_norm; mant8 = mant_norm; }
    } else {
        exp8 = 0u; mant8 = 0u;         // underflow
    }

    // ---- emit 8 bit-pulses: [S, E3..E0, M2..M0] ----
    float4 o0 = make_float4((float)s,
                            (float)((exp8 >> 3) & 1u),
                            (float)((exp8 >> 2) & 1u),
                            (float)((exp8 >> 1) & 1u));
    float4 o1 = make_float4((float)(exp8 & 1u),
                            (float)((mant8 >> 2) & 1u),
                            (float)((mant8 >> 1) & 1u),
                            (float)(mant8 & 1u));

    float4* op = reinterpret_cast<float4*>(out + (size_t)(base + lane) * 8);
    __stcs(&op[0], o0);    // streaming store
    __stcs(&op[1], o1);
}

extern "C" void kernel_launch(void* const* d_in, const int* in_sizes, int n_in,
                              void* d_out, int out_size)
{
    const float* in  = (const float*)d_in[0];
    float*       out = (float*)d_out;
    const int nvals  = in_sizes[0] / 32;       // 2,097,152

    const int threads = 512;                   // 16 warps -> 512 values per block
    const int blocks = (nvals + threads - 1) / threads;

    fp32_to_fp8_pulse_kernel<<<blocks, threads>>>(in, out, nvals);
}